// round 4
// baseline (speedup 1.0000x reference)
#include <cuda_runtime.h>

#define NN 100000
#define NF 512
#define NH 16
#define NC 40
#define NE 3200000

// Scratch (no allocations allowed -> __device__ globals)
__device__ float g_dinv[NN];          // degree, then rsqrt(degree)
__device__ float g_feat[NN * NH];     // pre-scaled features (message payload)
__device__ float g_agg[NN * NH];      // aggregation accumulator

// ---------------------------------------------------------------- degree
__global__ void k_deg_init() {
    int i = blockIdx.x * blockDim.x + threadIdx.x;
    if (i < NN) g_dinv[i] = 1.0f;   // self-loop
}

__global__ void k_deg_count(const int* __restrict__ dst) {
    int e = blockIdx.x * blockDim.x + threadIdx.x;
    if (e < NE) atomicAdd(&g_dinv[dst[e]], 1.0f);  // exact integer-valued float adds
}

__global__ void k_rsqrt() {
    int i = blockIdx.x * blockDim.x + threadIdx.x;
    if (i < NN) g_dinv[i] = rsqrtf(g_dinv[i]);
}

// ---------------------------------------------------------------- GEMM1: h = (x @ W1) * dinv
// 128 threads, 2 nodes/thread (256 nodes per CTA, grid=391).
// x loaded straight to registers (LDG.128, one 32B sector per node per chunk),
// W broadcast from shared via LDS.64, packed f32x2 FMAs, no staging / no syncs
// in the main loop.
__global__ __launch_bounds__(128) void k_gemm1(const float* __restrict__ x,
                                               const float* __restrict__ W1) {
    __shared__ float Ws[NF * NH];     // 32 KB
    const int tid  = threadIdx.x;
    const int base = blockIdx.x * 256;
    const int n0 = base + tid;
    const int n1 = base + 128 + tid;

    for (int i = tid; i < NF * NH; i += 128) Ws[i] = W1[i];
    __syncthreads();
    const unsigned long long* Ws2 = reinterpret_cast<const unsigned long long*>(Ws);

    // clamp OOB rows to a safe dummy (stores are guarded)
    const int m0 = n0 < NN ? n0 : 0;
    const int m1 = n1 < NN ? n1 : 0;
    const float4* xa = reinterpret_cast<const float4*>(x + (size_t)m0 * NF);
    const float4* xb = reinterpret_cast<const float4*>(x + (size_t)m1 * NF);

    unsigned long long accA[8], accB[8];
#pragma unroll
    for (int j = 0; j < 8; j++) { accA[j] = 0ull; accB[j] = 0ull; }

    for (int cb = 0; cb < NF / 4; cb += 2) {     // 8 k-columns per iteration
        float4 a0 = xa[cb], a1 = xa[cb + 1];
        float4 b0 = xb[cb], b1 = xb[cb + 1];
        float av[8] = {a0.x, a0.y, a0.z, a0.w, a1.x, a1.y, a1.z, a1.w};
        float bv[8] = {b0.x, b0.y, b0.z, b0.w, b1.x, b1.y, b1.z, b1.w};
#pragma unroll
        for (int c = 0; c < 8; c++) {
            unsigned au = __float_as_uint(av[c]);
            unsigned bu = __float_as_uint(bv[c]);
            unsigned long long a2, b2;
            asm("mov.b64 %0, {%1, %1};" : "=l"(a2) : "r"(au));
            asm("mov.b64 %0, {%1, %1};" : "=l"(b2) : "r"(bu));
            const int k = cb * 4 + c;
#pragma unroll
            for (int j = 0; j < 8; j++) {
                unsigned long long w2 = Ws2[k * 8 + j];    // broadcast LDS.64
                asm("fma.rn.f32x2 %0, %1, %2, %0;" : "+l"(accA[j]) : "l"(a2), "l"(w2));
                asm("fma.rn.f32x2 %0, %1, %2, %0;" : "+l"(accB[j]) : "l"(b2), "l"(w2));
            }
        }
    }

    // epilogue for both nodes
#pragma unroll
    for (int half = 0; half < 2; half++) {
        int node = half ? n1 : n0;
        if (node >= NN) continue;
        unsigned long long* acc = half ? accB : accA;
        float dv = g_dinv[node];
        float o[16];
#pragma unroll
        for (int j = 0; j < 8; j++) {
            unsigned lo, hi;
            asm("mov.b64 {%0, %1}, %2;" : "=r"(lo), "=r"(hi) : "l"(acc[j]));
            o[2 * j]     = __uint_as_float(lo) * dv;
            o[2 * j + 1] = __uint_as_float(hi) * dv;
        }
        float4* f = (float4*)(g_feat + (size_t)node * NH);
        float4* a = (float4*)(g_agg  + (size_t)node * NH);
#pragma unroll
        for (int q = 0; q < 4; q++) {
            float4 v = make_float4(o[4*q], o[4*q+1], o[4*q+2], o[4*q+3]);
            f[q] = v;
            a[q] = v;   // self-loop contribution (pre-scaled)
        }
    }
}

// ---------------------------------------------------------------- edge scatter: agg[dst] += feat[src]
__device__ __forceinline__ void red_add_v4(float* p, float4 v) {
    asm volatile("red.global.add.v4.f32 [%0], {%1,%2,%3,%4};"
                 :: "l"(p), "f"(v.x), "f"(v.y), "f"(v.z), "f"(v.w) : "memory");
}

__global__ void k_scatter(const int* __restrict__ src, const int* __restrict__ dst) {
    int e = blockIdx.x * blockDim.x + threadIdx.x;
    if (e >= NE) return;
    int s = src[e], d = dst[e];
    const float4* h = (const float4*)(g_feat + (size_t)s * NH);
    float4 a = h[0], b = h[1], c = h[2], w = h[3];
    float* o = g_agg + (size_t)d * NH;
    red_add_v4(o,      a);
    red_add_v4(o + 4,  b);
    red_add_v4(o + 8,  c);
    red_add_v4(o + 12, w);
}

// ---------------------------------------------------------------- mid: g = relu(dinv*agg + b1) * dinv
__global__ void k_mid(const float* __restrict__ b1) {
    int i = blockIdx.x * blockDim.x + threadIdx.x;
    if (i >= NN) return;
    float dv = g_dinv[i];
    float4* a = (float4*)(g_agg  + (size_t)i * NH);
    float4* f = (float4*)(g_feat + (size_t)i * NH);
#pragma unroll
    for (int q = 0; q < 4; q++) {
        float4 v = a[q];
        float4 w;
        w.x = fmaxf(fmaf(v.x, dv, __ldg(b1 + 4*q + 0)), 0.f) * dv;
        w.y = fmaxf(fmaf(v.y, dv, __ldg(b1 + 4*q + 1)), 0.f) * dv;
        w.z = fmaxf(fmaf(v.z, dv, __ldg(b1 + 4*q + 2)), 0.f) * dv;
        w.w = fmaxf(fmaf(v.w, dv, __ldg(b1 + 4*q + 3)), 0.f) * dv;
        f[q] = w;       // message payload for layer 2
        a[q] = w;       // self-loop init for layer-2 accumulator
    }
}

// ---------------------------------------------------------------- out: log_softmax(dinv*agg @ W2 + b2)
__global__ __launch_bounds__(256) void k_out(const float* __restrict__ W2,
                                             const float* __restrict__ b2,
                                             float* __restrict__ out) {
    __shared__ float Ws[NH * NC];   // 2.5 KB
    __shared__ float bs[NC];
    int tid = threadIdx.x;
    for (int i = tid; i < NH * NC; i += 256) Ws[i] = W2[i];
    if (tid < NC) bs[tid] = b2[tid];
    __syncthreads();

    int i = blockIdx.x * 256 + tid;
    if (i >= NN) return;
    float dv = g_dinv[i];

    float v[NH];
    const float4* a = (const float4*)(g_agg + (size_t)i * NH);
#pragma unroll
    for (int q = 0; q < 4; q++) {
        float4 t = a[q];
        v[4*q+0] = t.x * dv; v[4*q+1] = t.y * dv;
        v[4*q+2] = t.z * dv; v[4*q+3] = t.w * dv;
    }

    float o[NC];
    float m = -1e30f;
#pragma unroll
    for (int k = 0; k < NC; k++) {
        float s = bs[k];
#pragma unroll
        for (int j = 0; j < NH; j++) s = fmaf(v[j], Ws[j * NC + k], s);
        o[k] = s;
        m = fmaxf(m, s);
    }
    float sum = 0.f;
#pragma unroll
    for (int k = 0; k < NC; k++) sum += __expf(o[k] - m);
    float l = m + logf(sum);

    float4* op = (float4*)(out + (size_t)i * NC);
#pragma unroll
    for (int q = 0; q < 10; q++) {
        op[q] = make_float4(o[4*q] - l, o[4*q+1] - l, o[4*q+2] - l, o[4*q+3] - l);
    }
}

// ----------------------------------------------------------------
extern "C" void kernel_launch(void* const* d_in, const int* in_sizes, int n_in,
                              void* d_out, int out_size) {
    const float* x  = (const float*)d_in[0];
    const int*   ei = (const int*)d_in[1];
    const float* W1 = (const float*)d_in[2];
    const float* b1 = (const float*)d_in[3];
    const float* W2 = (const float*)d_in[4];
    const float* b2 = (const float*)d_in[5];
    float* out = (float*)d_out;

    const int* src = ei;        // edge_index[0]
    const int* dst = ei + NE;   // edge_index[1]

    const int NB_N  = (NN + 255) / 256;   // 391
    const int NB_E  = (NE + 255) / 256;   // 12500
    const int NB_G  = (NN + 255) / 256;   // 391 CTAs x 256 nodes

    k_deg_init<<<NB_N, 256>>>();
    k_deg_count<<<NB_E, 256>>>(dst);
    k_rsqrt<<<NB_N, 256>>>();
    k_gemm1<<<NB_G, 128>>>(x, W1);
    k_scatter<<<NB_E, 256>>>(src, dst);
    k_mid<<<NB_N, 256>>>(b1);
    k_scatter<<<NB_E, 256>>>(src, dst);
    k_out<<<NB_N, 256>>>(W2, b2, out);
}

// round 8
// speedup vs baseline: 1.0625x; 1.0625x over previous
#include <cuda_runtime.h>

#define NN 100000
#define NF 512
#define NH 16
#define NC 40
#define NE 3200000
#define KCH 4            // split-K chunks
#define KC  (NF / KCH)   // 128 cols per chunk

// Scratch (no allocations allowed -> __device__ globals)
__device__ float g_dinv[NN];            // degree, then rsqrt(degree)
__device__ float g_feat[NN * NH];       // pre-scaled features (message payload)
__device__ float g_agg[NN * NH];        // aggregation accumulator
__device__ float g_part[KCH][NN * NH];  // split-K partial sums (deterministic)

// ---------------------------------------------------------------- degree
__global__ void k_deg_init() {
    int i = blockIdx.x * blockDim.x + threadIdx.x;
    if (i < NN) g_dinv[i] = 1.0f;   // self-loop
}

__global__ void k_deg_count(const int* __restrict__ dst) {
    int e = blockIdx.x * blockDim.x + threadIdx.x;
    if (e < NE) atomicAdd(&g_dinv[dst[e]], 1.0f);  // exact integer-valued float adds
}

__global__ void k_rsqrt() {
    int i = blockIdx.x * blockDim.x + threadIdx.x;
    if (i < NN) g_dinv[i] = rsqrtf(g_dinv[i]);
}

// ---------------------------------------------------------------- GEMM1 (split-K):
// grid (391, 4), 256 threads. CTA (b, c): nodes [b*256, b*256+256), k-cols
// [c*128, c*128+128). Partials -> g_part[c]. 4x warp parallelism vs node-only
// decomposition; 4-deep batched LDG.128 per iteration for MLP.
__global__ __launch_bounds__(256) void k_gemm1(const float* __restrict__ x,
                                               const float* __restrict__ W1) {
    __shared__ float Ws[KC * NH];    // 8 KB
    const int tid   = threadIdx.x;
    const int chunk = blockIdx.y;
    const int node  = blockIdx.x * 256 + tid;

    for (int i = tid; i < KC * NH; i += 256) Ws[i] = W1[chunk * KC * NH + i];
    __syncthreads();
    const unsigned long long* Ws2 = reinterpret_cast<const unsigned long long*>(Ws);

    const int m = node < NN ? node : 0;
    const float4* xp = reinterpret_cast<const float4*>(x + (size_t)m * NF + chunk * KC);

    unsigned long long acc[8];
#pragma unroll
    for (int j = 0; j < 8; j++) acc[j] = 0ull;

#pragma unroll 2
    for (int it = 0; it < KC / 16; it++) {       // 8 iters, 16 k-cols each
        float4 v[4];
#pragma unroll
        for (int q = 0; q < 4; q++) v[q] = xp[it * 4 + q];   // 64B batched
#pragma unroll
        for (int q = 0; q < 4; q++) {
            float vv[4] = {v[q].x, v[q].y, v[q].z, v[q].w};
#pragma unroll
            for (int c = 0; c < 4; c++) {
                const int k = it * 16 + q * 4 + c;
                unsigned xu = __float_as_uint(vv[c]);
                unsigned long long x2;
                asm("mov.b64 %0, {%1, %1};" : "=l"(x2) : "r"(xu));
#pragma unroll
                for (int j = 0; j < 8; j++) {
                    unsigned long long w2 = Ws2[k * 8 + j];   // broadcast LDS.64
                    asm("fma.rn.f32x2 %0, %1, %2, %0;" : "+l"(acc[j]) : "l"(x2), "l"(w2));
                }
            }
        }
    }

    if (node < NN) {
        float4* p = (float4*)(&g_part[chunk][(size_t)node * NH]);
#pragma unroll
        for (int q = 0; q < 4; q++) {
            unsigned lo0, hi0, lo1, hi1;
            asm("mov.b64 {%0, %1}, %2;" : "=r"(lo0), "=r"(hi0) : "l"(acc[2*q]));
            asm("mov.b64 {%0, %1}, %2;" : "=r"(lo1), "=r"(hi1) : "l"(acc[2*q+1]));
            p[q] = make_float4(__uint_as_float(lo0), __uint_as_float(hi0),
                               __uint_as_float(lo1), __uint_as_float(hi1));
        }
    }
}

// ---------------------------------------------------------------- combine partials:
// feat = agg = (sum_c part[c]) * dinv   (self-loop contribution pre-scaled)
__global__ void k_combine() {
    int i = blockIdx.x * blockDim.x + threadIdx.x;
    if (i >= NN) return;
    float dv = g_dinv[i];
    const float4* p0 = (const float4*)(&g_part[0][(size_t)i * NH]);
    const float4* p1 = (const float4*)(&g_part[1][(size_t)i * NH]);
    const float4* p2 = (const float4*)(&g_part[2][(size_t)i * NH]);
    const float4* p3 = (const float4*)(&g_part[3][(size_t)i * NH]);
    float4* f = (float4*)(g_feat + (size_t)i * NH);
    float4* a = (float4*)(g_agg  + (size_t)i * NH);
#pragma unroll
    for (int q = 0; q < 4; q++) {
        float4 s0 = p0[q], s1 = p1[q], s2 = p2[q], s3 = p3[q];
        float4 v;
        v.x = ((s0.x + s1.x) + (s2.x + s3.x)) * dv;
        v.y = ((s0.y + s1.y) + (s2.y + s3.y)) * dv;
        v.z = ((s0.z + s1.z) + (s2.z + s3.z)) * dv;
        v.w = ((s0.w + s1.w) + (s2.w + s3.w)) * dv;
        f[q] = v;
        a[q] = v;
    }
}

// ---------------------------------------------------------------- edge scatter: agg[dst] += feat[src]
__device__ __forceinline__ void red_add_v4(float* p, float4 v) {
    asm volatile("red.global.add.v4.f32 [%0], {%1,%2,%3,%4};"
                 :: "l"(p), "f"(v.x), "f"(v.y), "f"(v.z), "f"(v.w) : "memory");
}

__global__ void k_scatter(const int* __restrict__ src, const int* __restrict__ dst) {
    int e = blockIdx.x * blockDim.x + threadIdx.x;
    if (e >= NE) return;
    int s = src[e], d = dst[e];
    const float4* h = (const float4*)(g_feat + (size_t)s * NH);
    float4 a = h[0], b = h[1], c = h[2], w = h[3];
    float* o = g_agg + (size_t)d * NH;
    red_add_v4(o,      a);
    red_add_v4(o + 4,  b);
    red_add_v4(o + 8,  c);
    red_add_v4(o + 12, w);
}

// ---------------------------------------------------------------- mid: g = relu(dinv*agg + b1) * dinv
__global__ void k_mid(const float* __restrict__ b1) {
    int i = blockIdx.x * blockDim.x + threadIdx.x;
    if (i >= NN) return;
    float dv = g_dinv[i];
    float4* a = (float4*)(g_agg  + (size_t)i * NH);
    float4* f = (float4*)(g_feat + (size_t)i * NH);
#pragma unroll
    for (int q = 0; q < 4; q++) {
        float4 v = a[q];
        float4 w;
        w.x = fmaxf(fmaf(v.x, dv, __ldg(b1 + 4*q + 0)), 0.f) * dv;
        w.y = fmaxf(fmaf(v.y, dv, __ldg(b1 + 4*q + 1)), 0.f) * dv;
        w.z = fmaxf(fmaf(v.z, dv, __ldg(b1 + 4*q + 2)), 0.f) * dv;
        w.w = fmaxf(fmaf(v.w, dv, __ldg(b1 + 4*q + 3)), 0.f) * dv;
        f[q] = w;       // message payload for layer 2
        a[q] = w;       // self-loop init for layer-2 accumulator
    }
}

// ---------------------------------------------------------------- out: log_softmax(dinv*agg @ W2 + b2)
__global__ __launch_bounds__(256) void k_out(const float* __restrict__ W2,
                                             const float* __restrict__ b2,
                                             float* __restrict__ out) {
    __shared__ float Ws[NH * NC];   // 2.5 KB
    __shared__ float bs[NC];
    int tid = threadIdx.x;
    for (int i = tid; i < NH * NC; i += 256) Ws[i] = W2[i];
    if (tid < NC) bs[tid] = b2[tid];
    __syncthreads();

    int i = blockIdx.x * 256 + tid;
    if (i >= NN) return;
    float dv = g_dinv[i];

    float v[NH];
    const float4* a = (const float4*)(g_agg + (size_t)i * NH);
#pragma unroll
    for (int q = 0; q < 4; q++) {
        float4 t = a[q];
        v[4*q+0] = t.x * dv; v[4*q+1] = t.y * dv;
        v[4*q+2] = t.z * dv; v[4*q+3] = t.w * dv;
    }

    float o[NC];
    float m = -1e30f;
#pragma unroll
    for (int k = 0; k < NC; k++) {
        float s = bs[k];
#pragma unroll
        for (int j = 0; j < NH; j++) s = fmaf(v[j], Ws[j * NC + k], s);
        o[k] = s;
        m = fmaxf(m, s);
    }
    float sum = 0.f;
#pragma unroll
    for (int k = 0; k < NC; k++) sum += __expf(o[k] - m);
    float l = m + logf(sum);

    float4* op = (float4*)(out + (size_t)i * NC);
#pragma unroll
    for (int q = 0; q < 10; q++) {
        op[q] = make_float4(o[4*q] - l, o[4*q+1] - l, o[4*q+2] - l, o[4*q+3] - l);
    }
}

// ----------------------------------------------------------------
extern "C" void kernel_launch(void* const* d_in, const int* in_sizes, int n_in,
                              void* d_out, int out_size) {
    const float* x  = (const float*)d_in[0];
    const int*   ei = (const int*)d_in[1];
    const float* W1 = (const float*)d_in[2];
    const float* b1 = (const float*)d_in[3];
    const float* W2 = (const float*)d_in[4];
    const float* b2 = (const float*)d_in[5];
    float* out = (float*)d_out;

    const int* src = ei;        // edge_index[0]
    const int* dst = ei + NE;   // edge_index[1]

    const int NB_N = (NN + 255) / 256;   // 391
    const int NB_E = (NE + 255) / 256;   // 12500

    k_deg_init<<<NB_N, 256>>>();
    k_deg_count<<<NB_E, 256>>>(dst);
    k_rsqrt<<<NB_N, 256>>>();
    k_gemm1<<<dim3(NB_N, KCH), 256>>>(x, W1);
    k_combine<<<NB_N, 256>>>();
    k_scatter<<<NB_E, 256>>>(src, dst);
    k_mid<<<NB_N, 256>>>(b1);
    k_scatter<<<NB_E, 256>>>(src, dst);
    k_out<<<NB_N, 256>>>(W2, b2, out);
}

// round 9
// speedup vs baseline: 1.2992x; 1.2227x over previous
#include <cuda_runtime.h>

#define NN 100000
#define NF 512
#define NH 16
#define NC 40
#define NE 3200000
#define KCH 4            // split-K chunks
#define KC  (NF / KCH)   // 128 cols per chunk
#define SCB 1024         // scan block size
#define NSB ((NN + SCB - 1) / SCB)   // 98 scan blocks

// Scratch (no allocations allowed -> __device__ globals)
__device__ float g_dinv[NN];
__device__ float g_feat[NN * NH];       // layer-1 messages, later final agg2
__device__ float g_agg[NN * NH];        // layer-2 messages
__device__ float g_part[KCH][NN * NH];  // split-K partials (deterministic)
__device__ int   g_deg[NN];
__device__ int   g_scan[NN];            // block-local inclusive scan
__device__ int   g_rows[NN + 1];        // CSR row offsets
__device__ int   g_cursor[NN];          // fill cursors
__device__ int   g_csr[NE];             // CSR column (src) indices
__device__ int   g_bsum[NSB];
__device__ int   g_boff[NSB];

// ---------------------------------------------------------------- degree
__global__ void k_zero() {
    int i = blockIdx.x * blockDim.x + threadIdx.x;
    if (i < NN) g_deg[i] = 0;
}

__global__ void k_deg(const int* __restrict__ dst) {
    int e = blockIdx.x * blockDim.x + threadIdx.x;
    if (e < NE) atomicAdd(&g_deg[dst[e]], 1);
}

// ---------------------------------------------------------------- prefix scan (3 stages)
__global__ __launch_bounds__(SCB) void k_scan1() {
    __shared__ int s[SCB];
    int t = threadIdx.x;
    int i = blockIdx.x * SCB + t;
    int v = (i < NN) ? g_deg[i] : 0;
    s[t] = v;
    __syncthreads();
#pragma unroll
    for (int off = 1; off < SCB; off <<= 1) {
        int u = (t >= off) ? s[t - off] : 0;
        __syncthreads();
        s[t] += u;
        __syncthreads();
    }
    if (i < NN) g_scan[i] = s[t];
    if (t == SCB - 1) g_bsum[blockIdx.x] = s[t];
}

__global__ __launch_bounds__(128) void k_scan2() {
    __shared__ int s[128];
    int t = threadIdx.x;
    int v = (t < NSB) ? g_bsum[t] : 0;
    s[t] = v;
    __syncthreads();
#pragma unroll
    for (int off = 1; off < 128; off <<= 1) {
        int u = (t >= off) ? s[t - off] : 0;
        __syncthreads();
        s[t] += u;
        __syncthreads();
    }
    if (t < NSB) g_boff[t] = s[t] - v;   // exclusive block offsets
}

__global__ void k_scan3() {
    int i = blockIdx.x * blockDim.x + threadIdx.x;
    if (i >= NN) return;
    int d = g_deg[i];
    int excl = g_scan[i] - d + g_boff[i >> 10];
    g_rows[i] = excl;
    g_cursor[i] = excl;
    g_dinv[i] = rsqrtf((float)(d + 1));   // +1 self-loop
    if (i == 0) g_rows[NN] = NE;
}

// ---------------------------------------------------------------- CSR fill
__global__ void k_fill(const int* __restrict__ src, const int* __restrict__ dst) {
    int e = blockIdx.x * blockDim.x + threadIdx.x;
    if (e >= NE) return;
    int pos = atomicAdd(&g_cursor[dst[e]], 1);
    g_csr[pos] = src[e];
}

// ---------------------------------------------------------------- GEMM1 (split-K, 2 nodes/thread):
// grid (196, 4), 256 threads. CTA (b,c): nodes [b*512, b*512+512), k-cols
// [c*128, +128). One broadcast LDS.64 of W feeds 2 FMAs (halved LDS stream).
__global__ __launch_bounds__(256) void k_gemm1(const float* __restrict__ x,
                                               const float* __restrict__ W1) {
    __shared__ float Ws[KC * NH];    // 8 KB
    const int tid   = threadIdx.x;
    const int chunk = blockIdx.y;
    const int n0 = blockIdx.x * 512 + tid;
    const int n1 = n0 + 256;

    for (int i = tid; i < KC * NH; i += 256) Ws[i] = W1[chunk * KC * NH + i];
    __syncthreads();
    const unsigned long long* Ws2 = reinterpret_cast<const unsigned long long*>(Ws);

    const int m0 = n0 < NN ? n0 : 0;
    const int m1 = n1 < NN ? n1 : 0;
    const float4* xa = reinterpret_cast<const float4*>(x + (size_t)m0 * NF + chunk * KC);
    const float4* xb = reinterpret_cast<const float4*>(x + (size_t)m1 * NF + chunk * KC);

    unsigned long long accA[8], accB[8];
#pragma unroll
    for (int j = 0; j < 8; j++) { accA[j] = 0ull; accB[j] = 0ull; }

#pragma unroll 2
    for (int it = 0; it < KC / 8; it++) {       // 16 iters, 8 k-cols each
        float4 a0 = xa[it * 2], a1 = xa[it * 2 + 1];    // 4 batched LDG.128
        float4 b0 = xb[it * 2], b1 = xb[it * 2 + 1];
        float av[8] = {a0.x, a0.y, a0.z, a0.w, a1.x, a1.y, a1.z, a1.w};
        float bv[8] = {b0.x, b0.y, b0.z, b0.w, b1.x, b1.y, b1.z, b1.w};
#pragma unroll
        for (int c = 0; c < 8; c++) {
            const int k = it * 8 + c;
            unsigned long long a2, b2;
            asm("mov.b64 %0, {%1, %1};" : "=l"(a2) : "r"(__float_as_uint(av[c])));
            asm("mov.b64 %0, {%1, %1};" : "=l"(b2) : "r"(__float_as_uint(bv[c])));
#pragma unroll
            for (int j = 0; j < 8; j++) {
                unsigned long long w2 = Ws2[k * 8 + j];   // broadcast LDS.64
                asm("fma.rn.f32x2 %0, %1, %2, %0;" : "+l"(accA[j]) : "l"(a2), "l"(w2));
                asm("fma.rn.f32x2 %0, %1, %2, %0;" : "+l"(accB[j]) : "l"(b2), "l"(w2));
            }
        }
    }

#pragma unroll
    for (int half = 0; half < 2; half++) {
        int node = half ? n1 : n0;
        if (node >= NN) continue;
        unsigned long long* acc = half ? accB : accA;
        float4* p = (float4*)(&g_part[chunk][(size_t)node * NH]);
#pragma unroll
        for (int q = 0; q < 4; q++) {
            unsigned lo0, hi0, lo1, hi1;
            asm("mov.b64 {%0, %1}, %2;" : "=r"(lo0), "=r"(hi0) : "l"(acc[2*q]));
            asm("mov.b64 {%0, %1}, %2;" : "=r"(lo1), "=r"(hi1) : "l"(acc[2*q+1]));
            p[q] = make_float4(__uint_as_float(lo0), __uint_as_float(hi0),
                               __uint_as_float(lo1), __uint_as_float(hi1));
        }
    }
}

// ---------------------------------------------------------------- combine: feat = (sum parts) * dinv
__global__ void k_combine() {
    int i = blockIdx.x * blockDim.x + threadIdx.x;
    if (i >= NN) return;
    float dv = g_dinv[i];
    const float4* p0 = (const float4*)(&g_part[0][(size_t)i * NH]);
    const float4* p1 = (const float4*)(&g_part[1][(size_t)i * NH]);
    const float4* p2 = (const float4*)(&g_part[2][(size_t)i * NH]);
    const float4* p3 = (const float4*)(&g_part[3][(size_t)i * NH]);
    float4* f = (float4*)(g_feat + (size_t)i * NH);
#pragma unroll
    for (int q = 0; q < 4; q++) {
        float4 s0 = p0[q], s1 = p1[q], s2 = p2[q], s3 = p3[q];
        float4 v;
        v.x = ((s0.x + s1.x) + (s2.x + s3.x)) * dv;
        v.y = ((s0.y + s1.y) + (s2.y + s3.y)) * dv;
        v.z = ((s0.z + s1.z) + (s2.z + s3.z)) * dv;
        v.w = ((s0.w + s1.w) + (s2.w + s3.w)) * dv;
        f[q] = v;
    }
}

// ---------------------------------------------------------------- CSR gather (warp per node)
// 16 lanes per neighbor: lane (half, f) reads in[nb*16+f] (64B coalesced per
// half-warp). acc register chain, shfl-reduce across halves.
// mode 0 (layer 1): out = relu(dinv*acc + b1) * dinv  -> g_agg (layer-2 msgs)
// mode 1 (layer 2): out = dinv*acc                    -> g_feat (final agg2)
__global__ __launch_bounds__(256) void k_gather(const float* __restrict__ b1, int mode) {
    int w = (blockIdx.x * 256 + threadIdx.x) >> 5;
    if (w >= NN) return;
    const int lane = threadIdx.x & 31;
    const int half = lane >> 4;
    const int f    = lane & 15;

    const float* __restrict__ in = mode ? g_agg : g_feat;
    int rs = g_rows[w], re = g_rows[w + 1];

    // self term counted once (half 0 only)
    float acc0 = half ? 0.0f : in[(size_t)w * NH + f];
    float acc1 = 0.0f;

    int c = rs;
    // 4 neighbors per iteration (2 per half), 2 independent accumulator chains
    for (; c + 4 <= re; c += 4) {
        int nb0 = __ldg(&g_csr[c + half]);
        int nb1 = __ldg(&g_csr[c + 2 + half]);
        float v0 = in[(size_t)nb0 * NH + f];
        float v1 = in[(size_t)nb1 * NH + f];
        acc0 += v0;
        acc1 += v1;
    }
    for (; c + half < re; c += 2) {
        int nb = __ldg(&g_csr[c + half]);
        acc0 += in[(size_t)nb * NH + f];
    }
    float acc = acc0 + acc1;
    acc += __shfl_down_sync(0xffffffffu, acc, 16);

    if (lane < 16) {
        float dv = g_dinv[w];
        float v = acc * dv;
        if (mode == 0) {
            v = fmaxf(v + __ldg(&b1[f]), 0.0f) * dv;
            g_agg[(size_t)w * NH + f] = v;
        } else {
            g_feat[(size_t)w * NH + f] = v;
        }
    }
}

// ---------------------------------------------------------------- out: log_softmax(agg2 @ W2 + b2)
__global__ __launch_bounds__(256) void k_out(const float* __restrict__ W2,
                                             const float* __restrict__ b2,
                                             float* __restrict__ out) {
    __shared__ float Ws[NH * NC];   // 2.5 KB
    __shared__ float bs[NC];
    int tid = threadIdx.x;
    for (int i = tid; i < NH * NC; i += 256) Ws[i] = W2[i];
    if (tid < NC) bs[tid] = b2[tid];
    __syncthreads();

    int i = blockIdx.x * 256 + tid;
    if (i >= NN) return;

    float v[NH];
    const float4* a = (const float4*)(g_feat + (size_t)i * NH);
#pragma unroll
    for (int q = 0; q < 4; q++) {
        float4 t = a[q];
        v[4*q+0] = t.x; v[4*q+1] = t.y; v[4*q+2] = t.z; v[4*q+3] = t.w;
    }

    float o[NC];
    float m = -1e30f;
#pragma unroll
    for (int k = 0; k < NC; k++) {
        float s = bs[k];
#pragma unroll
        for (int j = 0; j < NH; j++) s = fmaf(v[j], Ws[j * NC + k], s);
        o[k] = s;
        m = fmaxf(m, s);
    }
    float sum = 0.f;
#pragma unroll
    for (int k = 0; k < NC; k++) sum += __expf(o[k] - m);
    float l = m + logf(sum);

    float4* op = (float4*)(out + (size_t)i * NC);
#pragma unroll
    for (int q = 0; q < 10; q++) {
        op[q] = make_float4(o[4*q] - l, o[4*q+1] - l, o[4*q+2] - l, o[4*q+3] - l);
    }
}

// ----------------------------------------------------------------
extern "C" void kernel_launch(void* const* d_in, const int* in_sizes, int n_in,
                              void* d_out, int out_size) {
    const float* x  = (const float*)d_in[0];
    const int*   ei = (const int*)d_in[1];
    const float* W1 = (const float*)d_in[2];
    const float* b1 = (const float*)d_in[3];
    const float* W2 = (const float*)d_in[4];
    const float* b2 = (const float*)d_in[5];
    float* out = (float*)d_out;

    const int* src = ei;        // edge_index[0]
    const int* dst = ei + NE;   // edge_index[1]

    const int NB_N = (NN + 255) / 256;   // 391
    const int NB_E = (NE + 255) / 256;   // 12500
    const int NB_W = (NN * 32 + 255) / 256;  // 12500 (warp per node)

    k_zero<<<NB_N, 256>>>();
    k_deg<<<NB_E, 256>>>(dst);
    k_scan1<<<NSB, SCB>>>();
    k_scan2<<<1, 128>>>();
    k_scan3<<<NB_N, 256>>>();
    k_fill<<<NB_E, 256>>>(src, dst);
    k_gemm1<<<dim3((NN + 511) / 512, KCH), 256>>>(x, W1);
    k_combine<<<NB_N, 256>>>();
    k_gather<<<NB_W, 256>>>(b1, 0);   // layer 1 aggregate + relu + rescale
    k_gather<<<NB_W, 256>>>(b1, 1);   // layer 2 aggregate
    k_out<<<NB_N, 256>>>(W2, b2, out);
}